// round 3
// baseline (speedup 1.0000x reference)
#include <cuda_runtime.h>
#include <cstdint>

// Problem dims
#define B_DIM 256
#define S_DIM 512
#define I_DIM 64
#define H_DIM 256

// Parallel decomposition
#define CLUSTER 8        // CTAs per cluster
#define GBATCH 16        // batch rows per cluster
#define HSLICE 32        // hidden dims owned per CTA (256/8)
#define NCOL 128         // gate columns per CTA = 4*HSLICE
#define KTOT 320         // I_DIM + H_DIM
#define NTHREADS 128     // 4 warps; thread tile = 4 batch x 4 cols

// SMEM layout (bytes)
#define OFF_B 0
#define B_BYTES (KTOT * NCOL * 4)          // 163840: fused weights [320][128]
#define OFF_AX (OFF_B + B_BYTES)
#define AX_BYTES (I_DIM * 16 * 4)          // 4096: x_t panel [64][16]
#define OFF_AH (OFF_AX + AX_BYTES)
#define AHBUF_BYTES (H_DIM * 16 * 4)       // 16384: h panel [256][16]
#define SMEM_BYTES (OFF_AH + 2 * AHBUF_BYTES)  // 200704

__device__ __forceinline__ float sigf(float x) {
    return __fdividef(1.0f, 1.0f + __expf(-x));
}
__device__ __forceinline__ float tanh_(float x) {
    return __fdividef(2.0f, 1.0f + __expf(-2.0f * x)) - 1.0f;
}

__device__ __forceinline__ uint32_t smem_u32(const void* p) {
    uint32_t a;
    asm("{ .reg .u64 t; cvta.to.shared.u64 t, %1; cvt.u32.u64 %0, t; }"
        : "=r"(a) : "l"(p));
    return a;
}
__device__ __forceinline__ uint32_t mapa_u32(uint32_t addr, uint32_t rank) {
    uint32_t r;
    asm("mapa.shared::cluster.u32 %0, %1, %2;" : "=r"(r) : "r"(addr), "r"(rank));
    return r;
}
__device__ __forceinline__ void st_cluster_f2(uint32_t addr, float a, float b) {
    asm volatile("{ .reg .b64 v; mov.b64 v, {%1, %2}; st.shared::cluster.b64 [%0], v; }"
                 :: "r"(addr), "f"(a), "f"(b) : "memory");
}
#define CLUSTER_BAR() do { \
    asm volatile("barrier.cluster.arrive.aligned;" ::: "memory"); \
    asm volatile("barrier.cluster.wait.aligned;" ::: "memory"); \
} while (0)

__global__ void __cluster_dims__(CLUSTER, 1, 1) __launch_bounds__(NTHREADS, 1)
lstm_persist(const float* __restrict__ x,
             const float* __restrict__ w_i, const float* __restrict__ u_i, const float* __restrict__ b_i,
             const float* __restrict__ w_f, const float* __restrict__ u_f, const float* __restrict__ b_f,
             const float* __restrict__ w_c, const float* __restrict__ u_c, const float* __restrict__ b_c,
             const float* __restrict__ w_o, const float* __restrict__ u_o, const float* __restrict__ b_o,
             float* __restrict__ out)
{
    extern __shared__ char smem[];
    float* Bs = reinterpret_cast<float*>(smem + OFF_B);   // [320][128] fused W|U, gate-interleaved cols
    float* Ax = reinterpret_cast<float*>(smem + OFF_AX);  // [64][16]  x_t, k-major
    float* Ah = reinterpret_cast<float*>(smem + OFF_AH);  // [2][256][16] h panel, double buffered

    const int tid = threadIdx.x;
    const int lane = tid & 31;
    const int warp = tid >> 5;
    uint32_t rank;
    asm("mov.u32 %0, %%cluster_ctarank;" : "=r"(rank));
    const int gb = (blockIdx.x / CLUSTER) * GBATCH;   // global batch base for this cluster
    const int colh = (int)rank * HSLICE;              // base hidden dim owned by this CTA

    // ---- one-time: stage fused weights into SMEM: Bs[k][4*hd + g] ----
    // k < 64 -> W_g[k][colh+hd], else U_g[k-64][colh+hd]
    #pragma unroll
    for (int g = 0; g < 4; ++g) {
        const float* Wsrc = (g == 0) ? w_i : (g == 1) ? w_f : (g == 2) ? w_c : w_o;
        const float* Usrc = (g == 0) ? u_i : (g == 1) ? u_f : (g == 2) ? u_c : u_o;
        for (int k = warp; k < KTOT; k += 4) {
            const float* src = (k < I_DIM) ? (Wsrc + (size_t)k * H_DIM)
                                           : (Usrc + (size_t)(k - I_DIM) * H_DIM);
            Bs[k * NCOL + 4 * lane + g] = src[colh + lane];
        }
    }
    // zero h panel buffer 0 (h_0 = 0)
    for (int i = tid; i < H_DIM * 16; i += NTHREADS) Ah[i] = 0.0f;

    // thread tile: 4 batches x (4 gates of one hidden dim)
    const int hd = lane;            // hidden dim within slice (0..31)
    const int b0 = warp * 4;        // local batch base (0,4,8,12)

    const float bias0 = b_i[colh + hd];
    const float bias1 = b_f[colh + hd];
    const float bias2 = b_c[colh + hd];
    const float bias3 = b_o[colh + hd];

    // DSMEM push targets: this thread writes Ah[nb][colh+hd][b0..b0+3] in every cluster CTA
    const uint32_t sb = smem_u32(smem);
    const uint32_t loc = sb + OFF_AH + (uint32_t)(((colh + hd) * 16 + b0) * 4);
    uint32_t mb[CLUSTER];
    #pragma unroll
    for (int p = 0; p < CLUSTER; ++p) mb[p] = mapa_u32(loc, (uint32_t)p);

    float c0 = 0.f, c1 = 0.f, c2 = 0.f, c3 = 0.f;
    float h0 = 0.f, h1 = 0.f, h2 = 0.f, h3 = 0.f;

    // x staging: thread (bx, i0) loads 8 floats of x[gb+bx][t][i0..i0+7]
    const int bx = tid & 15;
    const int i0 = (tid >> 4) * 8;
    const float* xsrc = x + (size_t)(gb + bx) * S_DIM * I_DIM + i0;

    float4 xa = *reinterpret_cast<const float4*>(xsrc);
    float4 xb = *reinterpret_cast<const float4*>(xsrc + 4);

    __syncthreads();
    CLUSTER_BAR();

    int cur = 0;
    const float* Bcol = Bs + 4 * hd;

    for (int t = 0; t < S_DIM; ++t) {
        // stage prefetched x_t into Ax (k-major, batch contiguous)
        Ax[(i0 + 0) * 16 + bx] = xa.x;
        Ax[(i0 + 1) * 16 + bx] = xa.y;
        Ax[(i0 + 2) * 16 + bx] = xa.z;
        Ax[(i0 + 3) * 16 + bx] = xa.w;
        Ax[(i0 + 4) * 16 + bx] = xb.x;
        Ax[(i0 + 5) * 16 + bx] = xb.y;
        Ax[(i0 + 6) * 16 + bx] = xb.z;
        Ax[(i0 + 7) * 16 + bx] = xb.w;
        __syncthreads();

        // prefetch next timestep's x during the matmul
        if (t + 1 < S_DIM) {
            xa = *reinterpret_cast<const float4*>(xsrc + (size_t)(t + 1) * I_DIM);
            xb = *reinterpret_cast<const float4*>(xsrc + (size_t)(t + 1) * I_DIM + 4);
        }

        float4 acc0 = make_float4(bias0, bias1, bias2, bias3);
        float4 acc1 = acc0, acc2 = acc0, acc3 = acc0;

        // --- x part: [16,64] @ [64,128] slice ---
        const float* ax = Ax + b0;
        #pragma unroll 8
        for (int k = 0; k < I_DIM; ++k) {
            float4 av = *reinterpret_cast<const float4*>(ax + k * 16);
            float4 wv = *reinterpret_cast<const float4*>(Bcol + k * NCOL);
            acc0.x = fmaf(av.x, wv.x, acc0.x); acc0.y = fmaf(av.x, wv.y, acc0.y);
            acc0.z = fmaf(av.x, wv.z, acc0.z); acc0.w = fmaf(av.x, wv.w, acc0.w);
            acc1.x = fmaf(av.y, wv.x, acc1.x); acc1.y = fmaf(av.y, wv.y, acc1.y);
            acc1.z = fmaf(av.y, wv.z, acc1.z); acc1.w = fmaf(av.y, wv.w, acc1.w);
            acc2.x = fmaf(av.z, wv.x, acc2.x); acc2.y = fmaf(av.z, wv.y, acc2.y);
            acc2.z = fmaf(av.z, wv.z, acc2.z); acc2.w = fmaf(av.z, wv.w, acc2.w);
            acc3.x = fmaf(av.w, wv.x, acc3.x); acc3.y = fmaf(av.w, wv.y, acc3.y);
            acc3.z = fmaf(av.w, wv.z, acc3.z); acc3.w = fmaf(av.w, wv.w, acc3.w);
        }
        // --- h part: [16,256] @ [256,128] slice ---
        const float* ah = Ah + cur * (H_DIM * 16) + b0;
        const float* Bcol2 = Bcol + I_DIM * NCOL;
        #pragma unroll 8
        for (int k = 0; k < H_DIM; ++k) {
            float4 av = *reinterpret_cast<const float4*>(ah + k * 16);
            float4 wv = *reinterpret_cast<const float4*>(Bcol2 + k * NCOL);
            acc0.x = fmaf(av.x, wv.x, acc0.x); acc0.y = fmaf(av.x, wv.y, acc0.y);
            acc0.z = fmaf(av.x, wv.z, acc0.z); acc0.w = fmaf(av.x, wv.w, acc0.w);
            acc1.x = fmaf(av.y, wv.x, acc1.x); acc1.y = fmaf(av.y, wv.y, acc1.y);
            acc1.z = fmaf(av.y, wv.z, acc1.z); acc1.w = fmaf(av.y, wv.w, acc1.w);
            acc2.x = fmaf(av.z, wv.x, acc2.x); acc2.y = fmaf(av.z, wv.y, acc2.y);
            acc2.z = fmaf(av.z, wv.z, acc2.z); acc2.w = fmaf(av.z, wv.w, acc2.w);
            acc3.x = fmaf(av.w, wv.x, acc3.x); acc3.y = fmaf(av.w, wv.y, acc3.y);
            acc3.z = fmaf(av.w, wv.z, acc3.z); acc3.w = fmaf(av.w, wv.w, acc3.w);
        }

        // --- gates + state update (all thread-local) ---
        {
            float it = sigf(acc0.x), ft = sigf(acc0.y), gt = tanh_(acc0.z), ot = sigf(acc0.w);
            c0 = fmaf(ft, c0, it * gt);  h0 = ot * tanh_(c0);
        }
        {
            float it = sigf(acc1.x), ft = sigf(acc1.y), gt = tanh_(acc1.z), ot = sigf(acc1.w);
            c1 = fmaf(ft, c1, it * gt);  h1 = ot * tanh_(c1);
        }
        {
            float it = sigf(acc2.x), ft = sigf(acc2.y), gt = tanh_(acc2.z), ot = sigf(acc2.w);
            c2 = fmaf(ft, c2, it * gt);  h2 = ot * tanh_(c2);
        }
        {
            float it = sigf(acc3.x), ft = sigf(acc3.y), gt = tanh_(acc3.z), ot = sigf(acc3.w);
            c3 = fmaf(ft, c3, it * gt);  h3 = ot * tanh_(c3);
        }

        // write hidden_seq[t][b][colh+hd]
        float* op = out + (size_t)t * (B_DIM * H_DIM) + (size_t)(gb + b0) * H_DIM + (colh + hd);
        op[0]         = h0;
        op[H_DIM]     = h1;
        op[2 * H_DIM] = h2;
        op[3 * H_DIM] = h3;

        // push new h slice into all cluster CTAs' next A-panel
        const int nxt = cur ^ 1;
        const uint32_t off = (uint32_t)nxt * AHBUF_BYTES;
        #pragma unroll
        for (int p = 0; p < CLUSTER; ++p) {
            st_cluster_f2(mb[p] + off,     h0, h1);
            st_cluster_f2(mb[p] + off + 8, h2, h3);
        }
        cur = nxt;
        CLUSTER_BAR();  // release pushes, acquire peers' pushes
    }

    // final h_t, c_t
    float* out_h = out + (size_t)S_DIM * B_DIM * H_DIM;
    float* out_c = out_h + (size_t)B_DIM * H_DIM;
    const size_t fb = (size_t)(gb + b0) * H_DIM + (colh + hd);
    out_h[fb]             = h0;
    out_h[fb + H_DIM]     = h1;
    out_h[fb + 2 * H_DIM] = h2;
    out_h[fb + 3 * H_DIM] = h3;
    out_c[fb]             = c0;
    out_c[fb + H_DIM]     = c1;
    out_c[fb + 2 * H_DIM] = c2;
    out_c[fb + 3 * H_DIM] = c3;
}

extern "C" void kernel_launch(void* const* d_in, const int* in_sizes, int n_in,
                              void* d_out, int out_size) {
    const float* x   = (const float*)d_in[0];
    const float* w_i = (const float*)d_in[1];
    const float* u_i = (const float*)d_in[2];
    const float* b_i = (const float*)d_in[3];
    const float* w_f = (const float*)d_in[4];
    const float* u_f = (const float*)d_in[5];
    const float* b_f = (const float*)d_in[6];
    const float* w_c = (const float*)d_in[7];
    const float* u_c = (const float*)d_in[8];
    const float* b_c = (const float*)d_in[9];
    const float* w_o = (const float*)d_in[10];
    const float* u_o = (const float*)d_in[11];
    const float* b_o = (const float*)d_in[12];
    float* out = (float*)d_out;

    cudaFuncSetAttribute(lstm_persist,
                         cudaFuncAttributeMaxDynamicSharedMemorySize, SMEM_BYTES);

    dim3 grid((B_DIM / GBATCH) * CLUSTER);  // 16 clusters * 8 CTAs = 128
    lstm_persist<<<grid, NTHREADS, SMEM_BYTES>>>(
        x, w_i, u_i, b_i, w_f, u_f, b_f, w_c, u_c, b_c, w_o, u_o, b_o, out);
}